// round 11
// baseline (speedup 1.0000x reference)
#include <cuda_runtime.h>
#include <cuda_fp16.h>
#include <cstdint>

// ---------------- problem constants ----------------
#define BB 8
#define TT 256
#define UU 64
#define JJ 512          // K dim
#define VV 300          // vocab
#define NP 304          // padded vocab (mult of 8)
#define NTT 38          // joint n-tiles (NP/8)
#define NCHUNK 16       // K chunks of 32
#define BFRAG_U32 4864  // joint B frag u32 per chunk: 38 nt * 128

// ---------------- scratch (device globals; no allocs allowed) ----------------
__device__ __align__(16) float    g_enc_s[BB * TT * JJ];         // 4 MB   (enc projection out)
__device__ __align__(16) float    g_pred_s[BB * UU * JJ];        // 1 MB   (pred projection out)
__device__ __align__(16) uint32_t g_wfrag[NCHUNK * BFRAG_U32];   // 304 KB (W_out fp16 frags)
__device__ __align__(16) uint32_t g_wef[NCHUNK * 64 * 128];      // 512 KB (W_enc fp16 frags)
__device__ __align__(16) uint32_t g_wpf[NCHUNK * 64 * 128];      // 512 KB (W_pred fp16 frags)

// ---------------- helpers ----------------
__device__ __forceinline__ uint32_t smem_u32(const void* p) {
    uint32_t a;
    asm("{ .reg .u64 t; cvta.to.shared.u64 t, %1; cvt.u32.u64 %0, t; }" : "=r"(a) : "l"(p));
    return a;
}

__device__ __forceinline__ float tanh_ap(float x) {
    float y;
    asm("tanh.approx.f32 %0, %1;" : "=f"(y) : "f"(x));
    return y;
}

__device__ __forceinline__ uint32_t pack_h2(float lo, float hi) {
    half2 h = __floats2half2_rn(lo, hi);
    return *(uint32_t*)&h;
}

__device__ __forceinline__ void cp_async16(uint32_t dst, const void* gsrc) {
    uint64_t g;
    asm("cvta.to.global.u64 %0, %1;" : "=l"(g) : "l"(gsrc));
    asm volatile("cp.async.cg.shared.global [%0], [%1], 16;" :: "r"(dst), "l"(g) : "memory");
}
#define CP_COMMIT() asm volatile("cp.async.commit_group;" ::: "memory")
#define CP_WAIT0()  asm volatile("cp.async.wait_group 0;" ::: "memory")
#define CP_WAIT1()  asm volatile("cp.async.wait_group 1;" ::: "memory")
#define CP_WAIT2()  asm volatile("cp.async.wait_group 2;" ::: "memory")

__device__ __forceinline__ void mma_f16(float* d, const uint32_t* a, uint32_t b0, uint32_t b1) {
    asm volatile(
        "mma.sync.aligned.m16n8k16.row.col.f32.f16.f16.f32 "
        "{%0,%1,%2,%3}, {%4,%5,%6,%7}, {%8,%9}, {%0,%1,%2,%3};"
        : "+f"(d[0]), "+f"(d[1]), "+f"(d[2]), "+f"(d[3])
        : "r"(a[0]), "r"(a[1]), "r"(a[2]), "r"(a[3]), "r"(b0), "r"(b1));
}

// ---------------- kernel 1: all weights -> fp16 fragment-ready layout (one launch) ----------------
__global__ void prep_frag_kernel(const float* __restrict__ W_out,
                                 const float* __restrict__ W_enc,
                                 const float* __restrict__ W_pred) {
    const int z = blockIdx.y;
    const float* W; uint32_t* dst; int nt_total, n_valid;
    if (z == 0)      { W = W_out;  dst = g_wfrag; nt_total = NTT; n_valid = VV; }
    else if (z == 1) { W = W_enc;  dst = g_wef;   nt_total = 64;  n_valid = 512; }
    else             { W = W_pred; dst = g_wpf;   nt_total = 64;  n_valid = 512; }

    const int idx = blockIdx.x * 256 + threadIdx.x;
    const int per_chunk = nt_total * 128;
    if (idx >= NCHUNK * per_chunk) return;
    const int c   = idx / per_chunk;
    const int rem = idx - c * per_chunk;
    const int nt  = rem >> 7;
    const int r2  = rem & 127;
    const int lane = r2 >> 2;
    const int sub  = r2 & 3;
    const int ks = sub >> 1, reg = sub & 1;
    const int n = nt * 8 + (lane >> 2);
    const int k = c * 32 + ks * 16 + (lane & 3) * 2 + reg * 8;
    float lo = 0.0f, hi = 0.0f;
    if (n < n_valid) {
        float2 w = *(const float2*)(W + (size_t)n * JJ + k);
        lo = w.x; hi = w.y;
    }
    dst[idx] = pack_h2(lo, hi);
}

// ---------------- kernel 2: enc/pred projections (fp16 mma, fp32 accum) ----------------
static constexpr int P_OFF_A    = 0;
static constexpr int P_OFF_B    = 2048;
static constexpr int P_B_STRIDE = 8192;
static constexpr int P_SMEM     = P_OFF_B + 2 * P_B_STRIDE;   // 18432

__global__ __launch_bounds__(256, 4) void proj_kernel(
    const float* __restrict__ enc, const float* __restrict__ pred,
    const float* __restrict__ b_enc, const float* __restrict__ b_pred)
{
    extern __shared__ char smem[];
    const int tid = threadIdx.x;
    const int wid = tid >> 5, lane = tid & 31;
    const int bx = blockIdx.x, by = blockIdx.y;
    const int row0 = bx * 32;
    const bool isenc = (row0 < 2048);

    const float* __restrict__ X   = isenc ? (enc + (size_t)row0 * JJ) : (pred + (size_t)(row0 - 2048) * JJ);
    float*       __restrict__ Y   = isenc ? (g_enc_s + (size_t)row0 * JJ) : (g_pred_s + (size_t)(row0 - 2048) * JJ);
    const uint32_t* __restrict__ wf = isenc ? g_wef : g_wpf;
    const float* __restrict__ bias  = isenc ? b_enc : b_pred;

    const int f = tid >> 5, lf = tid & 31;
    const int pmt = f >> 1, pks = f & 1;
    const int prr = lf >> 2, pqf = lf & 3;
    const int m0 = pmt * 16 + prr, m1 = m0 + 8;
    const int cbase = pks * 16 + pqf * 2;
    const float* __restrict__ Xr0 = X + (size_t)m0 * JJ;
    const float* __restrict__ Xr1 = X + (size_t)m1 * JJ;
    char* Abuf = smem + P_OFF_A;
    const uint32_t Bsm = smem_u32(smem) + P_OFF_B;

    float acc[2][2][4];
    #pragma unroll
    for (int i = 0; i < 2; i++)
        #pragma unroll
        for (int j = 0; j < 2; j++)
            #pragma unroll
            for (int k = 0; k < 4; k++) acc[i][j][k] = 0.0f;

    {
        const char* src = (const char*)(wf + ((size_t)0 * 64 + by * 16) * 128);
        #pragma unroll
        for (int ii = 0; ii < 2; ii++)
            cp_async16(Bsm + (tid + ii * 256) * 16, src + (tid + ii * 256) * 16);
        CP_COMMIT();
    }

    #pragma unroll 1
    for (int c = 0; c < NCHUNK; c++) {
        const int buf = c & 1;
        if (c + 1 < NCHUNK) {
            const char* src = (const char*)(wf + ((size_t)(c + 1) * 64 + by * 16) * 128);
            const uint32_t d = Bsm + (buf ^ 1) * P_B_STRIDE;
            #pragma unroll
            for (int ii = 0; ii < 2; ii++)
                cp_async16(d + (tid + ii * 256) * 16, src + (tid + ii * 256) * 16);
            CP_COMMIT();
        }
        if (tid < 128) {
            const int c0 = c * 32 + cbase, c8 = c0 + 8;
            const float2 x0a = *(const float2*)(Xr0 + c0);
            const float2 x0b = *(const float2*)(Xr0 + c8);
            const float2 x1a = *(const float2*)(Xr1 + c0);
            const float2 x1b = *(const float2*)(Xr1 + c8);
            uint4 fr;
            fr.x = pack_h2(x0a.x, x0a.y);
            fr.y = pack_h2(x1a.x, x1a.y);
            fr.z = pack_h2(x0b.x, x0b.y);
            fr.w = pack_h2(x1b.x, x1b.y);
            *(uint4*)(Abuf + f * 512 + lf * 16) = fr;
        }
        if (c + 1 < NCHUNK) { CP_WAIT1(); } else { CP_WAIT0(); }
        __syncthreads();

        const char* Bb = smem + P_OFF_B + buf * P_B_STRIDE;
        const uint4 a00 = *(const uint4*)(Abuf + 0 * 512 + lane * 16);
        const uint4 a01 = *(const uint4*)(Abuf + 1 * 512 + lane * 16);
        const uint4 a10 = *(const uint4*)(Abuf + 2 * 512 + lane * 16);
        const uint4 a11 = *(const uint4*)(Abuf + 3 * 512 + lane * 16);
        const uint32_t A00[4] = {a00.x, a00.y, a00.z, a00.w};
        const uint32_t A01[4] = {a01.x, a01.y, a01.z, a01.w};
        const uint32_t A10[4] = {a10.x, a10.y, a10.z, a10.w};
        const uint32_t A11[4] = {a11.x, a11.y, a11.z, a11.w};
        #pragma unroll
        for (int j = 0; j < 2; j++) {
            const uint4 bq = *(const uint4*)(Bb + (wid * 2 + j) * 512 + lane * 16);
            mma_f16(acc[0][j], A00, bq.x, bq.y);
            mma_f16(acc[1][j], A10, bq.x, bq.y);
            mma_f16(acc[0][j], A01, bq.z, bq.w);
            mma_f16(acc[1][j], A11, bq.z, bq.w);
        }
        __syncthreads();
    }

    {
        const int rr = lane >> 2, qf = lane & 3;
        #pragma unroll
        for (int i = 0; i < 2; i++) {
            #pragma unroll
            for (int half = 0; half < 2; half++) {
                const int m = i * 16 + rr + half * 8;
                float* yrow = Y + (size_t)m * JJ;
                #pragma unroll
                for (int j = 0; j < 2; j++) {
                    const int n = by * 128 + wid * 16 + j * 8 + 2 * qf;
                    float2 o;
                    o.x = acc[i][j][half * 2 + 0] + bias[n];
                    o.y = acc[i][j][half * 2 + 1] + bias[n + 1];
                    *(float2*)(yrow + n) = o;
                }
            }
        }
    }
}

// ---------------- kernel 3: fused tanh-joint + vocab GEMM (fp16 mma, fp32 accum) ----------------
// Grid: 2048 CTAs = (b, t). CTA tile: M=64 (u) x N=304 x K=512. 256 thr = 8 warps,
// warp grid 4M x 2N: warp = 16 rows x 19 n-tiles (perfectly uniform, 38 MMA/chunk).
// Pipeline: A smem x2, B smem 4-slot cp.async ring (distance 2, wait_group 2),
// ONE __syncthreads per chunk. No register prefetch (keeps regs < 128). 2 CTAs/SM.
static constexpr int J_OFF_BIAS = 0;                        // 1216 B
static constexpr int J_OFF_A    = 2048;                     // 2 x 4096
static constexpr int J_A_STRIDE = 4096;
static constexpr int J_OFF_B    = 2048 + 2 * 4096;          // 10240
static constexpr int J_B_STRIDE = 19456;                    // 38 nt x 512B
static constexpr int J_SMEM     = J_OFF_B + 4 * J_B_STRIDE; // 88064 -> 2 CTAs/SM

__global__ __launch_bounds__(256, 2) void joint_kernel(const float* __restrict__ b_out,
                                                       float* __restrict__ out)
{
    extern __shared__ char smem[];
    const int tid  = threadIdx.x;
    const int wid  = tid >> 5;
    const int lane = tid & 31;
    const int b    = blockIdx.x >> 8;
    const int t    = blockIdx.x & 255;

    const int wm = wid & 3;          // 0..3 -> rows wm*16 .. +16
    const int wn = wid >> 2;         // 0..1 -> n-tiles wn*19 .. +19

    float* bias_sm = (float*)(smem + J_OFF_BIAS);
    #pragma unroll
    for (int i = 0; i < 2; i++) {
        const int n = tid + i * 256;
        if (n < NP) bias_sm[n] = (n < VV) ? b_out[n] : 0.0f;
    }

    const float* __restrict__ encR  = g_enc_s + (size_t)(b * TT + t) * JJ;
    const float* __restrict__ predB = g_pred_s + (size_t)b * UU * JJ;

    // producer indices (one frag-lane per thread: 8 frags x 32 lanes = 256)
    const int f = tid >> 5, lf = tid & 31;
    const int pmt = f >> 1, pks = f & 1;
    const int prr = lf >> 2, pqf = lf & 3;
    const int u0 = pmt * 16 + prr, u1 = u0 + 8;
    const int cbase = pks * 16 + pqf * 2;
    const float* __restrict__ pR0 = predB + (size_t)u0 * JJ;
    const float* __restrict__ pR1 = predB + (size_t)u1 * JJ;
    char* Abase = smem + J_OFF_A;
    const uint32_t Bsm = smem_u32(smem) + J_OFF_B;

    float acc[19][4];
    #pragma unroll
    for (int j = 0; j < 19; j++)
        #pragma unroll
        for (int k = 0; k < 4; k++) acc[j][k] = 0.0f;

    // prologue: B(0) -> slot0, B(1) -> slot1 (separate commit groups)
    #pragma unroll
    for (int pc = 0; pc < 2; pc++) {
        const char* src = (const char*)(g_wfrag + (size_t)pc * BFRAG_U32);
        const uint32_t d = Bsm + pc * J_B_STRIDE;
        #pragma unroll
        for (int ii = 0; ii < 5; ii++) {
            const int w = tid + ii * 256;
            if (w < 1216) cp_async16(d + w * 16, src + w * 16);
        }
        CP_COMMIT();
    }

    #pragma unroll 1
    for (int c = 0; c < NCHUNK; c++) {
        // ---- phase 1: produce A(c), prefetch B(c+2), no barrier inside ----
        char* Abuf = Abase + (c & 1) * J_A_STRIDE;
        {
            const int c0 = c * 32 + cbase, c8 = c0 + 8;
            const float2 ea  = *(const float2*)(encR + c0);
            const float2 eb  = *(const float2*)(encR + c8);
            const float2 p0a = *(const float2*)(pR0 + c0);
            const float2 p0b = *(const float2*)(pR0 + c8);
            const float2 p1a = *(const float2*)(pR1 + c0);
            const float2 p1b = *(const float2*)(pR1 + c8);
            uint4 fr;
            fr.x = pack_h2(tanh_ap(ea.x + p0a.x), tanh_ap(ea.y + p0a.y));
            fr.y = pack_h2(tanh_ap(ea.x + p1a.x), tanh_ap(ea.y + p1a.y));
            fr.z = pack_h2(tanh_ap(eb.x + p0b.x), tanh_ap(eb.y + p0b.y));
            fr.w = pack_h2(tanh_ap(eb.x + p1b.x), tanh_ap(eb.y + p1b.y));
            *(uint4*)(Abuf + f * 512 + lf * 16) = fr;
        }
        if (c + 2 < NCHUNK) {   // B(c+2) -> slot (c+2)&3
            const char* src = (const char*)(g_wfrag + (size_t)(c + 2) * BFRAG_U32);
            const uint32_t d = Bsm + ((c + 2) & 3) * J_B_STRIDE;
            #pragma unroll
            for (int ii = 0; ii < 5; ii++) {
                const int w = tid + ii * 256;
                if (w < 1216) cp_async16(d + w * 16, src + w * 16);
            }
            CP_COMMIT();
        }
        if (c + 2 < NCHUNK)      { CP_WAIT2(); }
        else if (c + 1 < NCHUNK) { CP_WAIT1(); }
        else                     { CP_WAIT0(); }
        __syncthreads();   // single barrier per chunk

        // ---- phase 2: 38 uniform MMAs on A(c), B(c) ----
        const char* Bb = smem + J_OFF_B + (c & 3) * J_B_STRIDE;
        const uint4 a0 = *(const uint4*)(Abuf + (wm * 2 + 0) * 512 + lane * 16);
        const uint4 a1 = *(const uint4*)(Abuf + (wm * 2 + 1) * 512 + lane * 16);
        const uint32_t A0[4] = {a0.x, a0.y, a0.z, a0.w};
        const uint32_t A1[4] = {a1.x, a1.y, a1.z, a1.w};
        const char* Bw = Bb + wn * 19 * 512 + lane * 16;
        #pragma unroll
        for (int nt = 0; nt < 19; nt++) {
            const uint4 bq = *(const uint4*)(Bw + nt * 512);
            mma_f16(acc[nt], A0, bq.x, bq.y);   // kstep 0
            mma_f16(acc[nt], A1, bq.z, bq.w);   // kstep 1
        }
    }

    // epilogue: bias add + guarded float2 stores
    {
        const int rr = lane >> 2, qf = lane & 3;
        #pragma unroll
        for (int half = 0; half < 2; half++) {
            const int u = wm * 16 + rr + half * 8;
            float* orow = out + (size_t)((b * TT + t) * UU + u) * VV;
            #pragma unroll
            for (int nt = 0; nt < 19; nt++) {
                const int n0 = (wn * 19 + nt) * 8 + 2 * qf;
                if (n0 < VV) {
                    float2 o;
                    o.x = acc[nt][half * 2 + 0] + bias_sm[n0];
                    o.y = acc[nt][half * 2 + 1] + bias_sm[n0 + 1];
                    *(float2*)(orow + n0) = o;
                }
            }
        }
    }
}

// ---------------- launch ----------------
extern "C" void kernel_launch(void* const* d_in, const int* in_sizes, int n_in,
                              void* d_out, int out_size) {
    const float* enc    = (const float*)d_in[0];
    const float* pred   = (const float*)d_in[1];
    const float* W_enc  = (const float*)d_in[2];
    const float* b_enc  = (const float*)d_in[3];
    const float* W_pred = (const float*)d_in[4];
    const float* b_pred = (const float*)d_in[5];
    const float* W_out  = (const float*)d_in[6];
    const float* b_out  = (const float*)d_in[7];
    float* out = (float*)d_out;

    cudaFuncSetAttribute(joint_kernel, cudaFuncAttributeMaxDynamicSharedMemorySize, J_SMEM);
    cudaFuncSetAttribute(proj_kernel,  cudaFuncAttributeMaxDynamicSharedMemorySize, P_SMEM);

    prep_frag_kernel<<<dim3(512, 3), 256>>>(W_out, W_enc, W_pred);
    proj_kernel<<<dim3(80, 4), 256, P_SMEM>>>(enc, pred, b_enc, b_pred);
    joint_kernel<<<BB * TT, 256, J_SMEM>>>(b_out, out);
}

// round 12
// speedup vs baseline: 1.1179x; 1.1179x over previous
#include <cuda_runtime.h>
#include <cuda_fp16.h>
#include <cstdint>

// ---------------- problem constants ----------------
#define BB 8
#define TT 256
#define UU 64
#define JJ 512          // K dim
#define VV 300          // vocab
#define NP 304          // padded vocab (mult of 8)
#define NTT 38          // joint n-tiles (NP/8)
#define NCHUNK 16       // prep/proj K chunks of 32
#define NCHUNK64 8      // joint K chunks of 64
#define BFRAG_U32 4864  // joint B frag u32 per chunk-32: 38 nt * 128

// ---------------- scratch (device globals; no allocs allowed) ----------------
__device__ __align__(16) float    g_enc_s[BB * TT * JJ];         // 4 MB   (enc projection out)
__device__ __align__(16) float    g_pred_s[BB * UU * JJ];        // 1 MB   (pred projection out)
__device__ __align__(16) uint32_t g_wfrag[NCHUNK * BFRAG_U32];   // 304 KB (W_out fp16 frags)
__device__ __align__(16) uint32_t g_wef[NCHUNK * 64 * 128];      // 512 KB (W_enc fp16 frags)
__device__ __align__(16) uint32_t g_wpf[NCHUNK * 64 * 128];      // 512 KB (W_pred fp16 frags)

// ---------------- helpers ----------------
__device__ __forceinline__ uint32_t smem_u32(const void* p) {
    uint32_t a;
    asm("{ .reg .u64 t; cvta.to.shared.u64 t, %1; cvt.u32.u64 %0, t; }" : "=r"(a) : "l"(p));
    return a;
}

__device__ __forceinline__ float tanh_ap(float x) {
    float y;
    asm("tanh.approx.f32 %0, %1;" : "=f"(y) : "f"(x));
    return y;
}

__device__ __forceinline__ uint32_t pack_h2(float lo, float hi) {
    half2 h = __floats2half2_rn(lo, hi);
    return *(uint32_t*)&h;
}

__device__ __forceinline__ void cp_async16(uint32_t dst, const void* gsrc) {
    uint64_t g;
    asm("cvta.to.global.u64 %0, %1;" : "=l"(g) : "l"(gsrc));
    asm volatile("cp.async.cg.shared.global [%0], [%1], 16;" :: "r"(dst), "l"(g) : "memory");
}
#define CP_COMMIT() asm volatile("cp.async.commit_group;" ::: "memory")
#define CP_WAIT0()  asm volatile("cp.async.wait_group 0;" ::: "memory")
#define CP_WAIT1()  asm volatile("cp.async.wait_group 1;" ::: "memory")

__device__ __forceinline__ void mma_f16(float* d, const uint32_t* a, uint32_t b0, uint32_t b1) {
    asm volatile(
        "mma.sync.aligned.m16n8k16.row.col.f32.f16.f16.f32 "
        "{%0,%1,%2,%3}, {%4,%5,%6,%7}, {%8,%9}, {%0,%1,%2,%3};"
        : "+f"(d[0]), "+f"(d[1]), "+f"(d[2]), "+f"(d[3])
        : "r"(a[0]), "r"(a[1]), "r"(a[2]), "r"(a[3]), "r"(b0), "r"(b1));
}

// ---------------- kernel 1: all weights -> fp16 fragment-ready layout (one launch) ----------------
__global__ void prep_frag_kernel(const float* __restrict__ W_out,
                                 const float* __restrict__ W_enc,
                                 const float* __restrict__ W_pred) {
    const int z = blockIdx.y;
    const float* W; uint32_t* dst; int nt_total, n_valid;
    if (z == 0)      { W = W_out;  dst = g_wfrag; nt_total = NTT; n_valid = VV; }
    else if (z == 1) { W = W_enc;  dst = g_wef;   nt_total = 64;  n_valid = 512; }
    else             { W = W_pred; dst = g_wpf;   nt_total = 64;  n_valid = 512; }

    const int idx = blockIdx.x * 256 + threadIdx.x;
    const int per_chunk = nt_total * 128;
    if (idx >= NCHUNK * per_chunk) return;
    const int c   = idx / per_chunk;
    const int rem = idx - c * per_chunk;
    const int nt  = rem >> 7;
    const int r2  = rem & 127;
    const int lane = r2 >> 2;
    const int sub  = r2 & 3;
    const int ks = sub >> 1, reg = sub & 1;
    const int n = nt * 8 + (lane >> 2);
    const int k = c * 32 + ks * 16 + (lane & 3) * 2 + reg * 8;
    float lo = 0.0f, hi = 0.0f;
    if (n < n_valid) {
        float2 w = *(const float2*)(W + (size_t)n * JJ + k);
        lo = w.x; hi = w.y;
    }
    dst[idx] = pack_h2(lo, hi);
}

// ---------------- kernel 2: enc/pred projections (fp16 mma, fp32 accum) ----------------
static constexpr int P_OFF_A    = 0;
static constexpr int P_OFF_B    = 2048;
static constexpr int P_B_STRIDE = 8192;
static constexpr int P_SMEM     = P_OFF_B + 2 * P_B_STRIDE;   // 18432

__global__ __launch_bounds__(256, 4) void proj_kernel(
    const float* __restrict__ enc, const float* __restrict__ pred,
    const float* __restrict__ b_enc, const float* __restrict__ b_pred)
{
    extern __shared__ char smem[];
    const int tid = threadIdx.x;
    const int wid = tid >> 5, lane = tid & 31;
    const int bx = blockIdx.x, by = blockIdx.y;
    const int row0 = bx * 32;
    const bool isenc = (row0 < 2048);

    const float* __restrict__ X   = isenc ? (enc + (size_t)row0 * JJ) : (pred + (size_t)(row0 - 2048) * JJ);
    float*       __restrict__ Y   = isenc ? (g_enc_s + (size_t)row0 * JJ) : (g_pred_s + (size_t)(row0 - 2048) * JJ);
    const uint32_t* __restrict__ wf = isenc ? g_wef : g_wpf;
    const float* __restrict__ bias  = isenc ? b_enc : b_pred;

    const int f = tid >> 5, lf = tid & 31;
    const int pmt = f >> 1, pks = f & 1;
    const int prr = lf >> 2, pqf = lf & 3;
    const int m0 = pmt * 16 + prr, m1 = m0 + 8;
    const int cbase = pks * 16 + pqf * 2;
    const float* __restrict__ Xr0 = X + (size_t)m0 * JJ;
    const float* __restrict__ Xr1 = X + (size_t)m1 * JJ;
    char* Abuf = smem + P_OFF_A;
    const uint32_t Bsm = smem_u32(smem) + P_OFF_B;

    float acc[2][2][4];
    #pragma unroll
    for (int i = 0; i < 2; i++)
        #pragma unroll
        for (int j = 0; j < 2; j++)
            #pragma unroll
            for (int k = 0; k < 4; k++) acc[i][j][k] = 0.0f;

    {
        const char* src = (const char*)(wf + ((size_t)0 * 64 + by * 16) * 128);
        #pragma unroll
        for (int ii = 0; ii < 2; ii++)
            cp_async16(Bsm + (tid + ii * 256) * 16, src + (tid + ii * 256) * 16);
        CP_COMMIT();
    }

    #pragma unroll 1
    for (int c = 0; c < NCHUNK; c++) {
        const int buf = c & 1;
        if (c + 1 < NCHUNK) {
            const char* src = (const char*)(wf + ((size_t)(c + 1) * 64 + by * 16) * 128);
            const uint32_t d = Bsm + (buf ^ 1) * P_B_STRIDE;
            #pragma unroll
            for (int ii = 0; ii < 2; ii++)
                cp_async16(d + (tid + ii * 256) * 16, src + (tid + ii * 256) * 16);
            CP_COMMIT();
        }
        if (tid < 128) {
            const int c0 = c * 32 + cbase, c8 = c0 + 8;
            const float2 x0a = *(const float2*)(Xr0 + c0);
            const float2 x0b = *(const float2*)(Xr0 + c8);
            const float2 x1a = *(const float2*)(Xr1 + c0);
            const float2 x1b = *(const float2*)(Xr1 + c8);
            uint4 fr;
            fr.x = pack_h2(x0a.x, x0a.y);
            fr.y = pack_h2(x1a.x, x1a.y);
            fr.z = pack_h2(x0b.x, x0b.y);
            fr.w = pack_h2(x1b.x, x1b.y);
            *(uint4*)(Abuf + f * 512 + lf * 16) = fr;
        }
        if (c + 1 < NCHUNK) { CP_WAIT1(); } else { CP_WAIT0(); }
        __syncthreads();

        const char* Bb = smem + P_OFF_B + buf * P_B_STRIDE;
        const uint4 a00 = *(const uint4*)(Abuf + 0 * 512 + lane * 16);
        const uint4 a01 = *(const uint4*)(Abuf + 1 * 512 + lane * 16);
        const uint4 a10 = *(const uint4*)(Abuf + 2 * 512 + lane * 16);
        const uint4 a11 = *(const uint4*)(Abuf + 3 * 512 + lane * 16);
        const uint32_t A00[4] = {a00.x, a00.y, a00.z, a00.w};
        const uint32_t A01[4] = {a01.x, a01.y, a01.z, a01.w};
        const uint32_t A10[4] = {a10.x, a10.y, a10.z, a10.w};
        const uint32_t A11[4] = {a11.x, a11.y, a11.z, a11.w};
        #pragma unroll
        for (int j = 0; j < 2; j++) {
            const uint4 bq = *(const uint4*)(Bb + (wid * 2 + j) * 512 + lane * 16);
            mma_f16(acc[0][j], A00, bq.x, bq.y);
            mma_f16(acc[1][j], A10, bq.x, bq.y);
            mma_f16(acc[0][j], A01, bq.z, bq.w);
            mma_f16(acc[1][j], A11, bq.z, bq.w);
        }
        __syncthreads();
    }

    {
        const int rr = lane >> 2, qf = lane & 3;
        #pragma unroll
        for (int i = 0; i < 2; i++) {
            #pragma unroll
            for (int half = 0; half < 2; half++) {
                const int m = i * 16 + rr + half * 8;
                float* yrow = Y + (size_t)m * JJ;
                #pragma unroll
                for (int j = 0; j < 2; j++) {
                    const int n = by * 128 + wid * 16 + j * 8 + 2 * qf;
                    float2 o;
                    o.x = acc[i][j][half * 2 + 0] + bias[n];
                    o.y = acc[i][j][half * 2 + 1] + bias[n + 1];
                    *(float2*)(yrow + n) = o;
                }
            }
        }
    }
}

// ---------------- kernel 3: fused tanh-joint + vocab GEMM (fp16 mma, fp32 accum) ----------------
// Grid: 2048 CTAs = (b, t). CTA tile: M=64 (u) x N=304 x K=512. 256 thr = 8 warps 2Mx4N
// (warps n0-2: 10 n-tiles, warp n3: 8). K chunk = 64 (8 chunks; 2 x chunk-32 images in smem).
// R7-proven pipeline: single A buffer, B double buffer (distance 1, wait_group 1),
// TWO __syncthreads per chunk. 2 CTAs/SM.
static constexpr int J_OFF_BIAS = 0;                        // 1216 B
static constexpr int J_OFF_A    = 2048;                     // 16 frags x 512B = 8192
static constexpr int J_OFF_B    = 2048 + 8192;              // 10240
static constexpr int J_B_HALF   = 19456;                    // one chunk-32 image (38 nt x 512B)
static constexpr int J_B_STRIDE = 2 * J_B_HALF;             // 38912 per chunk-64
static constexpr int J_SMEM     = J_OFF_B + 2 * J_B_STRIDE; // 88064 -> 2 CTAs/SM

__global__ __launch_bounds__(256, 2) void joint_kernel(const float* __restrict__ b_out,
                                                       float* __restrict__ out)
{
    extern __shared__ char smem[];
    const int tid  = threadIdx.x;
    const int wid  = tid >> 5;
    const int lane = tid & 31;
    const int b    = blockIdx.x >> 8;
    const int t    = blockIdx.x & 255;

    const int warp_m = wid >> 2;      // 0..1 -> rows warp_m*32 .. +32
    const int warp_n = wid & 3;       // 0..3
    const int ntbase = warp_n * 10;
    const int ntcnt  = (warp_n == 3) ? 8 : 10;   // 38 total
    const int mt0 = warp_m * 2, mt1 = warp_m * 2 + 1;

    float* bias_sm = (float*)(smem + J_OFF_BIAS);
    #pragma unroll
    for (int i = 0; i < 2; i++) {
        const int n = tid + i * 256;
        if (n < NP) bias_sm[n] = (n < VV) ? b_out[n] : 0.0f;
    }

    const float* __restrict__ encR  = g_enc_s + (size_t)(b * TT + t) * JJ;
    const float* __restrict__ predB = g_pred_s + (size_t)b * UU * JJ;

    // producer indices: thread handles frags g1 = tid>>5 (mt 0..1) and g1+8 (mt 2..3),
    // same ks = g1 & 3 for both -> enc column loads shared.
    const int g1  = tid >> 5, lf = tid & 31;
    const int pks = g1 & 3;
    const int mtA = g1 >> 2;              // 0..1
    const int prr = lf >> 2, pqf = lf & 3;
    const int uA0 = mtA * 16 + prr,        uA1 = uA0 + 8;
    const int uB0 = (mtA + 2) * 16 + prr,  uB1 = uB0 + 8;
    const int cbase = pks * 16 + pqf * 2;
    const float* __restrict__ pRA0 = predB + (size_t)uA0 * JJ;
    const float* __restrict__ pRA1 = predB + (size_t)uA1 * JJ;
    const float* __restrict__ pRB0 = predB + (size_t)uB0 * JJ;
    const float* __restrict__ pRB1 = predB + (size_t)uB1 * JJ;
    char* Abuf = smem + J_OFF_A;
    const uint32_t Bsm = smem_u32(smem) + J_OFF_B;

    float acc[2][10][4];
    #pragma unroll
    for (int i = 0; i < 2; i++)
        #pragma unroll
        for (int j = 0; j < 10; j++)
            #pragma unroll
            for (int k = 0; k < 4; k++) acc[i][j][k] = 0.0f;

    // prologue: B(0) (2432 uint4)
    {
        const char* src = (const char*)(g_wfrag);
        #pragma unroll
        for (int ii = 0; ii < 10; ii++) {
            const int w = tid + ii * 256;
            if (w < 2432) cp_async16(Bsm + w * 16, src + w * 16);
        }
        CP_COMMIT();
    }

    #pragma unroll 1
    for (int c = 0; c < NCHUNK64; c++) {
        const int buf = c & 1;
        if (c + 1 < NCHUNK64) {   // B(c+1) -> other buffer
            const char* src = (const char*)(g_wfrag + (size_t)(c + 1) * 2 * BFRAG_U32);
            const uint32_t d = Bsm + (buf ^ 1) * J_B_STRIDE;
            #pragma unroll
            for (int ii = 0; ii < 10; ii++) {
                const int w = tid + ii * 256;
                if (w < 2432) cp_async16(d + w * 16, src + w * 16);
            }
            CP_COMMIT();
        }
        // produce A(c): enc cols shared across the thread's two frags (10 LDG.64, 16 tanh, 2 STS.128)
        {
            const int c0 = c * 64 + cbase, c8 = c0 + 8;
            const float2 ea  = *(const float2*)(encR + c0);
            const float2 eb  = *(const float2*)(encR + c8);
            const float2 pa0 = *(const float2*)(pRA0 + c0);
            const float2 pa0b= *(const float2*)(pRA0 + c8);
            const float2 pa1 = *(const float2*)(pRA1 + c0);
            const float2 pa1b= *(const float2*)(pRA1 + c8);
            const float2 pb0 = *(const float2*)(pRB0 + c0);
            const float2 pb0b= *(const float2*)(pRB0 + c8);
            const float2 pb1 = *(const float2*)(pRB1 + c0);
            const float2 pb1b= *(const float2*)(pRB1 + c8);
            uint4 fr;
            fr.x = pack_h2(tanh_ap(ea.x + pa0.x),  tanh_ap(ea.y + pa0.y));
            fr.y = pack_h2(tanh_ap(ea.x + pa1.x),  tanh_ap(ea.y + pa1.y));
            fr.z = pack_h2(tanh_ap(eb.x + pa0b.x), tanh_ap(eb.y + pa0b.y));
            fr.w = pack_h2(tanh_ap(eb.x + pa1b.x), tanh_ap(eb.y + pa1b.y));
            *(uint4*)(Abuf + g1 * 512 + lf * 16) = fr;
            uint4 fr2;
            fr2.x = pack_h2(tanh_ap(ea.x + pb0.x),  tanh_ap(ea.y + pb0.y));
            fr2.y = pack_h2(tanh_ap(ea.x + pb1.x),  tanh_ap(ea.y + pb1.y));
            fr2.z = pack_h2(tanh_ap(eb.x + pb0b.x), tanh_ap(eb.y + pb0b.y));
            fr2.w = pack_h2(tanh_ap(eb.x + pb1b.x), tanh_ap(eb.y + pb1b.y));
            *(uint4*)(Abuf + (g1 + 8) * 512 + lf * 16) = fr2;
        }
        if (c + 1 < NCHUNK64) { CP_WAIT1(); } else { CP_WAIT0(); }
        __syncthreads();

        // MMA phase: two 32-col halves; frag id = mt*4 + ks (ks = 2h, 2h+1)
        const char* Bb = smem + J_OFF_B + buf * J_B_STRIDE;
        #pragma unroll
        for (int h = 0; h < 2; h++) {
            const char* Bh = Bb + h * J_B_HALF;
            const uint4 a00 = *(const uint4*)(Abuf + (mt0 * 4 + 2 * h + 0) * 512 + lane * 16);
            const uint4 a01 = *(const uint4*)(Abuf + (mt0 * 4 + 2 * h + 1) * 512 + lane * 16);
            const uint4 a10 = *(const uint4*)(Abuf + (mt1 * 4 + 2 * h + 0) * 512 + lane * 16);
            const uint4 a11 = *(const uint4*)(Abuf + (mt1 * 4 + 2 * h + 1) * 512 + lane * 16);
            const uint32_t A00[4] = {a00.x, a00.y, a00.z, a00.w};
            const uint32_t A01[4] = {a01.x, a01.y, a01.z, a01.w};
            const uint32_t A10[4] = {a10.x, a10.y, a10.z, a10.w};
            const uint32_t A11[4] = {a11.x, a11.y, a11.z, a11.w};
            #pragma unroll
            for (int nt = 0; nt < 10; nt++) {
                if (nt < ntcnt) {
                    const uint4 bq = *(const uint4*)(Bh + (ntbase + nt) * 512 + lane * 16);
                    mma_f16(acc[0][nt], A00, bq.x, bq.y);   // kstep 2h
                    mma_f16(acc[1][nt], A10, bq.x, bq.y);
                    mma_f16(acc[0][nt], A01, bq.z, bq.w);   // kstep 2h+1
                    mma_f16(acc[1][nt], A11, bq.z, bq.w);
                }
            }
        }
        __syncthreads();
    }

    // epilogue: bias add + guarded float2 stores
    {
        const int rr = lane >> 2, qf = lane & 3;
        #pragma unroll
        for (int i = 0; i < 2; i++) {
            #pragma unroll
            for (int half = 0; half < 2; half++) {
                const int u = warp_m * 32 + i * 16 + rr + half * 8;
                float* orow = out + (size_t)((b * TT + t) * UU + u) * VV;
                #pragma unroll
                for (int nt = 0; nt < 10; nt++) {
                    const int n0 = (ntbase + nt) * 8 + 2 * qf;
                    if (nt < ntcnt && n0 < VV) {
                        float2 o;
                        o.x = acc[i][nt][half * 2 + 0] + bias_sm[n0];
                        o.y = acc[i][nt][half * 2 + 1] + bias_sm[n0 + 1];
                        *(float2*)(orow + n0) = o;
                    }
                }
            }
        }
    }
}

// ---------------- launch ----------------
extern "C" void kernel_launch(void* const* d_in, const int* in_sizes, int n_in,
                              void* d_out, int out_size) {
    const float* enc    = (const float*)d_in[0];
    const float* pred   = (const float*)d_in[1];
    const float* W_enc  = (const float*)d_in[2];
    const float* b_enc  = (const float*)d_in[3];
    const float* W_pred = (const float*)d_in[4];
    const float* b_pred = (const float*)d_in[5];
    const float* W_out  = (const float*)d_in[6];
    const float* b_out  = (const float*)d_in[7];
    float* out = (float*)d_out;

    cudaFuncSetAttribute(joint_kernel, cudaFuncAttributeMaxDynamicSharedMemorySize, J_SMEM);
    cudaFuncSetAttribute(proj_kernel,  cudaFuncAttributeMaxDynamicSharedMemorySize, P_SMEM);

    prep_frag_kernel<<<dim3(512, 3), 256>>>(W_out, W_enc, W_pred);
    proj_kernel<<<dim3(80, 4), 256, P_SMEM>>>(enc, pred, b_enc, b_pred);
    joint_kernel<<<BB * TT, 256, J_SMEM>>>(b_out, out);
}

// round 13
// speedup vs baseline: 1.1392x; 1.0191x over previous
#include <cuda_runtime.h>
#include <cuda_fp16.h>
#include <cstdint>

// ---------------- problem constants ----------------
#define BB 8
#define TT 256
#define UU 64
#define JJ 512          // K dim
#define VV 300          // vocab
#define NP 304          // padded vocab (mult of 8)
#define NTT 38          // joint n-tiles (NP/8)
#define NCHUNK 16       // prep/proj K chunks of 32
#define NCHUNK64 8      // joint K chunks of 64
#define BFRAG_U32 4864  // joint B frag u32 per chunk-32: 38 nt * 128

// ---------------- scratch (device globals; no allocs allowed) ----------------
__device__ __align__(16) float    g_enc_s[BB * TT * JJ];         // 4 MB   (enc projection out)
__device__ __align__(16) float    g_pred_s[BB * UU * JJ];        // 1 MB   (pred projection out)
__device__ __align__(16) uint32_t g_wfrag[NCHUNK * BFRAG_U32];   // 304 KB (W_out fp16 frags)
__device__ __align__(16) uint32_t g_wef[NCHUNK * 64 * 128];      // 512 KB (W_enc fp16 frags)
__device__ __align__(16) uint32_t g_wpf[NCHUNK * 64 * 128];      // 512 KB (W_pred fp16 frags)

// ---------------- helpers ----------------
__device__ __forceinline__ uint32_t smem_u32(const void* p) {
    uint32_t a;
    asm("{ .reg .u64 t; cvta.to.shared.u64 t, %1; cvt.u32.u64 %0, t; }" : "=r"(a) : "l"(p));
    return a;
}

__device__ __forceinline__ float tanh_ap(float x) {
    float y;
    asm("tanh.approx.f32 %0, %1;" : "=f"(y) : "f"(x));
    return y;
}

__device__ __forceinline__ uint32_t pack_h2(float lo, float hi) {
    half2 h = __floats2half2_rn(lo, hi);
    return *(uint32_t*)&h;
}

__device__ __forceinline__ void cp_async16(uint32_t dst, const void* gsrc) {
    uint64_t g;
    asm("cvta.to.global.u64 %0, %1;" : "=l"(g) : "l"(gsrc));
    asm volatile("cp.async.cg.shared.global [%0], [%1], 16;" :: "r"(dst), "l"(g) : "memory");
}
#define CP_COMMIT() asm volatile("cp.async.commit_group;" ::: "memory")
#define CP_WAIT0()  asm volatile("cp.async.wait_group 0;" ::: "memory")
#define CP_WAIT1()  asm volatile("cp.async.wait_group 1;" ::: "memory")

__device__ __forceinline__ void mma_f16(float* d, const uint32_t* a, uint32_t b0, uint32_t b1) {
    asm volatile(
        "mma.sync.aligned.m16n8k16.row.col.f32.f16.f16.f32 "
        "{%0,%1,%2,%3}, {%4,%5,%6,%7}, {%8,%9}, {%0,%1,%2,%3};"
        : "+f"(d[0]), "+f"(d[1]), "+f"(d[2]), "+f"(d[3])
        : "r"(a[0]), "r"(a[1]), "r"(a[2]), "r"(a[3]), "r"(b0), "r"(b1));
}

// shared frag-conversion body (W row-major fp32 -> fp16 frag layout)
__device__ __forceinline__ void frag_convert(const float* __restrict__ W, uint32_t* __restrict__ dst,
                                             int nt_total, int n_valid, int idx) {
    const int per_chunk = nt_total * 128;
    if (idx >= NCHUNK * per_chunk) return;
    const int c   = idx / per_chunk;
    const int rem = idx - c * per_chunk;
    const int nt  = rem >> 7;
    const int r2  = rem & 127;
    const int lane = r2 >> 2;
    const int sub  = r2 & 3;
    const int ks = sub >> 1, reg = sub & 1;
    const int n = nt * 8 + (lane >> 2);
    const int k = c * 32 + ks * 16 + (lane & 3) * 2 + reg * 8;
    float lo = 0.0f, hi = 0.0f;
    if (n < n_valid) {
        float2 w = *(const float2*)(W + (size_t)n * JJ + k);
        lo = w.x; hi = w.y;
    }
    dst[idx] = pack_h2(lo, hi);
}

// ---------------- kernel 1: W_enc / W_pred -> fp16 fragment layout ----------------
__global__ void prep_frag_kernel(const float* __restrict__ W_enc,
                                 const float* __restrict__ W_pred) {
    const int z = blockIdx.y;
    frag_convert(z ? W_pred : W_enc, z ? g_wpf : g_wef, 64, 512,
                 blockIdx.x * 256 + threadIdx.x);
}

// ---------------- kernel 2: enc/pred projections + (blocks >= 320) W_out frag prep ----------------
static constexpr int P_OFF_A    = 0;
static constexpr int P_OFF_B    = 2048;
static constexpr int P_B_STRIDE = 8192;
static constexpr int P_SMEM     = P_OFF_B + 2 * P_B_STRIDE;   // 18432
static constexpr int P_PROJ_BLKS = 320;                       // 80 row-tiles x 4 n-tiles
static constexpr int P_WFRAG_BLKS = (NCHUNK * BFRAG_U32 + 255) / 256;  // 304

__global__ __launch_bounds__(256, 4) void proj_kernel(
    const float* __restrict__ enc, const float* __restrict__ pred,
    const float* __restrict__ b_enc, const float* __restrict__ b_pred,
    const float* __restrict__ W_out)
{
    extern __shared__ char smem[];
    const int tid = threadIdx.x;

    if (blockIdx.x >= P_PROJ_BLKS) {   // W_out fragment conversion (overlaps proj mma work)
        frag_convert(W_out, g_wfrag, NTT, VV,
                     (blockIdx.x - P_PROJ_BLKS) * 256 + tid);
        return;
    }

    const int wid = tid >> 5, lane = tid & 31;
    const int bx = blockIdx.x / 4, by = blockIdx.x & 3;
    const int row0 = bx * 32;
    const bool isenc = (row0 < 2048);

    const float* __restrict__ X   = isenc ? (enc + (size_t)row0 * JJ) : (pred + (size_t)(row0 - 2048) * JJ);
    float*       __restrict__ Y   = isenc ? (g_enc_s + (size_t)row0 * JJ) : (g_pred_s + (size_t)(row0 - 2048) * JJ);
    const uint32_t* __restrict__ wf = isenc ? g_wef : g_wpf;
    const float* __restrict__ bias  = isenc ? b_enc : b_pred;

    const int f = tid >> 5, lf = tid & 31;
    const int pmt = f >> 1, pks = f & 1;
    const int prr = lf >> 2, pqf = lf & 3;
    const int m0 = pmt * 16 + prr, m1 = m0 + 8;
    const int cbase = pks * 16 + pqf * 2;
    const float* __restrict__ Xr0 = X + (size_t)m0 * JJ;
    const float* __restrict__ Xr1 = X + (size_t)m1 * JJ;
    char* Abuf = smem + P_OFF_A;
    const uint32_t Bsm = smem_u32(smem) + P_OFF_B;

    float acc[2][2][4];
    #pragma unroll
    for (int i = 0; i < 2; i++)
        #pragma unroll
        for (int j = 0; j < 2; j++)
            #pragma unroll
            for (int k = 0; k < 4; k++) acc[i][j][k] = 0.0f;

    {
        const char* src = (const char*)(wf + ((size_t)0 * 64 + by * 16) * 128);
        #pragma unroll
        for (int ii = 0; ii < 2; ii++)
            cp_async16(Bsm + (tid + ii * 256) * 16, src + (tid + ii * 256) * 16);
        CP_COMMIT();
    }

    #pragma unroll 1
    for (int c = 0; c < NCHUNK; c++) {
        const int buf = c & 1;
        if (c + 1 < NCHUNK) {
            const char* src = (const char*)(wf + ((size_t)(c + 1) * 64 + by * 16) * 128);
            const uint32_t d = Bsm + (buf ^ 1) * P_B_STRIDE;
            #pragma unroll
            for (int ii = 0; ii < 2; ii++)
                cp_async16(d + (tid + ii * 256) * 16, src + (tid + ii * 256) * 16);
            CP_COMMIT();
        }
        if (tid < 128) {
            const int c0 = c * 32 + cbase, c8 = c0 + 8;
            const float2 x0a = *(const float2*)(Xr0 + c0);
            const float2 x0b = *(const float2*)(Xr0 + c8);
            const float2 x1a = *(const float2*)(Xr1 + c0);
            const float2 x1b = *(const float2*)(Xr1 + c8);
            uint4 fr;
            fr.x = pack_h2(x0a.x, x0a.y);
            fr.y = pack_h2(x1a.x, x1a.y);
            fr.z = pack_h2(x0b.x, x0b.y);
            fr.w = pack_h2(x1b.x, x1b.y);
            *(uint4*)(Abuf + f * 512 + lf * 16) = fr;
        }
        if (c + 1 < NCHUNK) { CP_WAIT1(); } else { CP_WAIT0(); }
        __syncthreads();

        const char* Bb = smem + P_OFF_B + buf * P_B_STRIDE;
        const uint4 a00 = *(const uint4*)(Abuf + 0 * 512 + lane * 16);
        const uint4 a01 = *(const uint4*)(Abuf + 1 * 512 + lane * 16);
        const uint4 a10 = *(const uint4*)(Abuf + 2 * 512 + lane * 16);
        const uint4 a11 = *(const uint4*)(Abuf + 3 * 512 + lane * 16);
        const uint32_t A00[4] = {a00.x, a00.y, a00.z, a00.w};
        const uint32_t A01[4] = {a01.x, a01.y, a01.z, a01.w};
        const uint32_t A10[4] = {a10.x, a10.y, a10.z, a10.w};
        const uint32_t A11[4] = {a11.x, a11.y, a11.z, a11.w};
        #pragma unroll
        for (int j = 0; j < 2; j++) {
            const uint4 bq = *(const uint4*)(Bb + (wid * 2 + j) * 512 + lane * 16);
            mma_f16(acc[0][j], A00, bq.x, bq.y);
            mma_f16(acc[1][j], A10, bq.x, bq.y);
            mma_f16(acc[0][j], A01, bq.z, bq.w);
            mma_f16(acc[1][j], A11, bq.z, bq.w);
        }
        __syncthreads();
    }

    {
        const int rr = lane >> 2, qf = lane & 3;
        #pragma unroll
        for (int i = 0; i < 2; i++) {
            #pragma unroll
            for (int half = 0; half < 2; half++) {
                const int m = i * 16 + rr + half * 8;
                float* yrow = Y + (size_t)m * JJ;
                #pragma unroll
                for (int j = 0; j < 2; j++) {
                    const int n = by * 128 + wid * 16 + j * 8 + 2 * qf;
                    float2 o;
                    o.x = acc[i][j][half * 2 + 0] + bias[n];
                    o.y = acc[i][j][half * 2 + 1] + bias[n + 1];
                    *(float2*)(yrow + n) = o;
                }
            }
        }
    }
}

// ---------------- kernel 3: fused tanh-joint + vocab GEMM (fp16 mma, fp32 accum) ----------------
// Grid: 2048 CTAs = (b, t). CTA tile: M=64 (u) x N=304 x K=512. 256 thr = 8 warps 2Mx4N
// (warps n0-2: 10 n-tiles, warp n3: 8 — split loops, no predicate). K chunk = 64.
// Single A buffer, B double buffer (distance 1, wait_group 1), 2 barriers/chunk. 2 CTAs/SM.
static constexpr int J_OFF_BIAS = 0;                        // 1216 B
static constexpr int J_OFF_A    = 2048;                     // 16 frags x 512B = 8192
static constexpr int J_OFF_B    = 2048 + 8192;              // 10240
static constexpr int J_B_HALF   = 19456;                    // one chunk-32 image (38 nt x 512B)
static constexpr int J_B_STRIDE = 2 * J_B_HALF;             // 38912 per chunk-64
static constexpr int J_SMEM     = J_OFF_B + 2 * J_B_STRIDE; // 88064 -> 2 CTAs/SM

__global__ __launch_bounds__(256, 2) void joint_kernel(const float* __restrict__ b_out,
                                                       float* __restrict__ out)
{
    extern __shared__ char smem[];
    const int tid  = threadIdx.x;
    const int wid  = tid >> 5;
    const int lane = tid & 31;
    const int b    = blockIdx.x >> 8;
    const int t    = blockIdx.x & 255;

    const int warp_m = wid >> 2;      // 0..1 -> rows warp_m*32 .. +32
    const int warp_n = wid & 3;       // 0..3
    const int ntbase = warp_n * 10;
    const int mt0 = warp_m * 2, mt1 = warp_m * 2 + 1;

    float* bias_sm = (float*)(smem + J_OFF_BIAS);
    #pragma unroll
    for (int i = 0; i < 2; i++) {
        const int n = tid + i * 256;
        if (n < NP) bias_sm[n] = (n < VV) ? b_out[n] : 0.0f;
    }

    const float* __restrict__ encR  = g_enc_s + (size_t)(b * TT + t) * JJ;
    const float* __restrict__ predB = g_pred_s + (size_t)b * UU * JJ;

    // producer indices: thread handles frags g1 = tid>>5 (mt 0..1) and g1+8 (mt 2..3),
    // same ks = g1 & 3 for both -> enc column loads shared.
    const int g1  = tid >> 5, lf = tid & 31;
    const int pks = g1 & 3;
    const int mtA = g1 >> 2;              // 0..1
    const int prr = lf >> 2, pqf = lf & 3;
    const int uA0 = mtA * 16 + prr,        uA1 = uA0 + 8;
    const int uB0 = (mtA + 2) * 16 + prr,  uB1 = uB0 + 8;
    const int cbase = pks * 16 + pqf * 2;
    const float* __restrict__ pRA0 = predB + (size_t)uA0 * JJ;
    const float* __restrict__ pRA1 = predB + (size_t)uA1 * JJ;
    const float* __restrict__ pRB0 = predB + (size_t)uB0 * JJ;
    const float* __restrict__ pRB1 = predB + (size_t)uB1 * JJ;
    char* Abuf = smem + J_OFF_A;
    const uint32_t Bsm = smem_u32(smem) + J_OFF_B;

    float acc[2][10][4];
    #pragma unroll
    for (int i = 0; i < 2; i++)
        #pragma unroll
        for (int j = 0; j < 10; j++)
            #pragma unroll
            for (int k = 0; k < 4; k++) acc[i][j][k] = 0.0f;

    // prologue: B(0) (2432 uint4)
    {
        const char* src = (const char*)(g_wfrag);
        #pragma unroll
        for (int ii = 0; ii < 10; ii++) {
            const int w = tid + ii * 256;
            if (w < 2432) cp_async16(Bsm + w * 16, src + w * 16);
        }
        CP_COMMIT();
    }

    #pragma unroll 1
    for (int c = 0; c < NCHUNK64; c++) {
        const int buf = c & 1;
        if (c + 1 < NCHUNK64) {   // B(c+1) -> other buffer
            const char* src = (const char*)(g_wfrag + (size_t)(c + 1) * 2 * BFRAG_U32);
            const uint32_t d = Bsm + (buf ^ 1) * J_B_STRIDE;
            #pragma unroll
            for (int ii = 0; ii < 10; ii++) {
                const int w = tid + ii * 256;
                if (w < 2432) cp_async16(d + w * 16, src + w * 16);
            }
            CP_COMMIT();
        }
        // produce A(c): enc cols shared across the thread's two frags (10 LDG.64, 16 tanh, 2 STS.128)
        {
            const int c0 = c * 64 + cbase, c8 = c0 + 8;
            const float2 ea  = *(const float2*)(encR + c0);
            const float2 eb  = *(const float2*)(encR + c8);
            const float2 pa0 = *(const float2*)(pRA0 + c0);
            const float2 pa0b= *(const float2*)(pRA0 + c8);
            const float2 pa1 = *(const float2*)(pRA1 + c0);
            const float2 pa1b= *(const float2*)(pRA1 + c8);
            const float2 pb0 = *(const float2*)(pRB0 + c0);
            const float2 pb0b= *(const float2*)(pRB0 + c8);
            const float2 pb1 = *(const float2*)(pRB1 + c0);
            const float2 pb1b= *(const float2*)(pRB1 + c8);
            uint4 fr;
            fr.x = pack_h2(tanh_ap(ea.x + pa0.x),  tanh_ap(ea.y + pa0.y));
            fr.y = pack_h2(tanh_ap(ea.x + pa1.x),  tanh_ap(ea.y + pa1.y));
            fr.z = pack_h2(tanh_ap(eb.x + pa0b.x), tanh_ap(eb.y + pa0b.y));
            fr.w = pack_h2(tanh_ap(eb.x + pa1b.x), tanh_ap(eb.y + pa1b.y));
            *(uint4*)(Abuf + g1 * 512 + lf * 16) = fr;
            uint4 fr2;
            fr2.x = pack_h2(tanh_ap(ea.x + pb0.x),  tanh_ap(ea.y + pb0.y));
            fr2.y = pack_h2(tanh_ap(ea.x + pb1.x),  tanh_ap(ea.y + pb1.y));
            fr2.z = pack_h2(tanh_ap(eb.x + pb0b.x), tanh_ap(eb.y + pb0b.y));
            fr2.w = pack_h2(tanh_ap(eb.x + pb1b.x), tanh_ap(eb.y + pb1b.y));
            *(uint4*)(Abuf + (g1 + 8) * 512 + lf * 16) = fr2;
        }
        if (c + 1 < NCHUNK64) { CP_WAIT1(); } else { CP_WAIT0(); }
        __syncthreads();

        // MMA phase: two 32-col halves; frag id = mt*4 + ks (ks = 2h, 2h+1)
        const char* Bb = smem + J_OFF_B + buf * J_B_STRIDE;
        #pragma unroll
        for (int h = 0; h < 2; h++) {
            const char* Bh = Bb + h * J_B_HALF;
            const uint4 a00 = *(const uint4*)(Abuf + (mt0 * 4 + 2 * h + 0) * 512 + lane * 16);
            const uint4 a01 = *(const uint4*)(Abuf + (mt0 * 4 + 2 * h + 1) * 512 + lane * 16);
            const uint4 a10 = *(const uint4*)(Abuf + (mt1 * 4 + 2 * h + 0) * 512 + lane * 16);
            const uint4 a11 = *(const uint4*)(Abuf + (mt1 * 4 + 2 * h + 1) * 512 + lane * 16);
            const uint32_t A00[4] = {a00.x, a00.y, a00.z, a00.w};
            const uint32_t A01[4] = {a01.x, a01.y, a01.z, a01.w};
            const uint32_t A10[4] = {a10.x, a10.y, a10.z, a10.w};
            const uint32_t A11[4] = {a11.x, a11.y, a11.z, a11.w};
            if (warp_n < 3) {
                #pragma unroll
                for (int nt = 0; nt < 10; nt++) {
                    const uint4 bq = *(const uint4*)(Bh + (ntbase + nt) * 512 + lane * 16);
                    mma_f16(acc[0][nt], A00, bq.x, bq.y);   // kstep 2h
                    mma_f16(acc[1][nt], A10, bq.x, bq.y);
                    mma_f16(acc[0][nt], A01, bq.z, bq.w);   // kstep 2h+1
                    mma_f16(acc[1][nt], A11, bq.z, bq.w);
                }
            } else {
                #pragma unroll
                for (int nt = 0; nt < 8; nt++) {
                    const uint4 bq = *(const uint4*)(Bh + (30 + nt) * 512 + lane * 16);
                    mma_f16(acc[0][nt], A00, bq.x, bq.y);
                    mma_f16(acc[1][nt], A10, bq.x, bq.y);
                    mma_f16(acc[0][nt], A01, bq.z, bq.w);
                    mma_f16(acc[1][nt], A11, bq.z, bq.w);
                }
            }
        }
        __syncthreads();
    }

    // epilogue: bias add + float2 stores (guard only where vocab edge can hit)
    {
        const int rr = lane >> 2, qf = lane & 3;
        #pragma unroll
        for (int i = 0; i < 2; i++) {
            #pragma unroll
            for (int half = 0; half < 2; half++) {
                const int u = warp_m * 32 + i * 16 + rr + half * 8;
                float* orow = out + (size_t)((b * TT + t) * UU + u) * VV;
                if (warp_n < 3) {
                    #pragma unroll
                    for (int nt = 0; nt < 10; nt++) {
                        const int n0 = (ntbase + nt) * 8 + 2 * qf;
                        float2 o;
                        o.x = acc[i][nt][half * 2 + 0] + bias_sm[n0];
                        o.y = acc[i][nt][half * 2 + 1] + bias_sm[n0 + 1];
                        *(float2*)(orow + n0) = o;
                    }
                } else {
                    #pragma unroll
                    for (int nt = 0; nt < 8; nt++) {
                        const int n0 = (30 + nt) * 8 + 2 * qf;
                        if (n0 < VV) {
                            float2 o;
                            o.x = acc[i][nt][half * 2 + 0] + bias_sm[n0];
                            o.y = acc[i][nt][half * 2 + 1] + bias_sm[n0 + 1];
                            *(float2*)(orow + n0) = o;
                        }
                    }
                }
            }
        }
    }
}

// ---------------- launch ----------------
extern "C" void kernel_launch(void* const* d_in, const int* in_sizes, int n_in,
                              void* d_out, int out_size) {
    const float* enc    = (const float*)d_in[0];
    const float* pred   = (const float*)d_in[1];
    const float* W_enc  = (const float*)d_in[2];
    const float* b_enc  = (const float*)d_in[3];
    const float* W_pred = (const float*)d_in[4];
    const float* b_pred = (const float*)d_in[5];
    const float* W_out  = (const float*)d_in[6];
    const float* b_out  = (const float*)d_in[7];
    float* out = (float*)d_out;

    cudaFuncSetAttribute(joint_kernel, cudaFuncAttributeMaxDynamicSharedMemorySize, J_SMEM);
    cudaFuncSetAttribute(proj_kernel,  cudaFuncAttributeMaxDynamicSharedMemorySize, P_SMEM);

    prep_frag_kernel<<<dim3(512, 2), 256>>>(W_enc, W_pred);
    proj_kernel<<<P_PROJ_BLKS + P_WFRAG_BLKS, 256, P_SMEM>>>(enc, pred, b_enc, b_pred, W_out);
    joint_kernel<<<BB * TT, 256, J_SMEM>>>(b_out, out);
}